// round 9
// baseline (speedup 1.0000x reference)
#include <cuda_runtime.h>

// ConvBertLightConv: dynamic depthwise conv, kernel=9, head=64.
// inputs:  [B=8, S=4096, D=768] fp32, filters: [B,S,108] fp32, out: [B,S,768].
//
// R8: 2-stage cp.async software pipeline. Each CTA walks 4 consecutive
// 32-position tiles; tile t+1's inputs+filters stream into the alternate
// smem stage while tile t is softmaxed/FMA'd/stored. The DRAM queue never
// drains inside a CTA. regs drop (no register-resident input tile) ->
// 8 CTAs/SM, occupancy ~50%.

#define S_LEN   4096
#define D_DIM   768
#define H_NUM   12
#define HD      64
#define KS      9
#define TILE_S  32
#define SREG    4
#define NTHREADS 128                  // 8 position-groups x 16 f4-columns
#define NTILES  4                     // tiles per CTA (sequential along S)
#define ROWS    (TILE_S + KS - 1)     // 40 staged rows per tile
#define ROW_F4  (D_DIM / 4)           // 192
#define FP      12                    // padded filter row stride (floats)

__device__ __forceinline__ void cp_async16z(void* smem, const void* gmem, int src_bytes) {
    unsigned sa = (unsigned)__cvta_generic_to_shared(smem);
    asm volatile("cp.async.ca.shared.global [%0], [%1], 16, %2;\n"
                 :: "r"(sa), "l"(gmem), "r"(src_bytes));
}
__device__ __forceinline__ void cp_async16(void* smem, const void* gmem) {
    unsigned sa = (unsigned)__cvta_generic_to_shared(smem);
    asm volatile("cp.async.ca.shared.global [%0], [%1], 16;\n"
                 :: "r"(sa), "l"(gmem));
}

__global__ __launch_bounds__(NTHREADS, 8)
void lightconv_kernel(const float* __restrict__ inputs,
                      const float* __restrict__ filters,
                      float* __restrict__ out)
{
    __shared__ float4 in_s[2][ROWS * 16];     // 2 x 10240 B
    __shared__ float  fraw[2][TILE_S * FP];   // 2 x 1536 B
    __shared__ float  w_s [TILE_S * FP];      // 1536 B

    const int tid = threadIdx.x;
    const int h   = blockIdx.y;
    const int b   = blockIdx.z;
    const int sbase = blockIdx.x * (TILE_S * NTILES);

    const int c   = tid & 15;                 // float4 column 0..15
    const int sl0 = (tid >> 4) * SREG;        // local base position 0..28

    const float4* in_g =
        (const float4*)(inputs + (size_t)b * S_LEN * D_DIM + h * HD);
    float4* out_g = (float4*)(out + (size_t)b * S_LEN * D_DIM + h * HD);

    const int foff  = h * KS;
    const int a0    = foff & ~3;              // aligned-down float offset
    const int shift = foff & 3;
    const float* f_g = filters + (size_t)(b * S_LEN) * (H_NUM * KS) + a0;

    // ---- stage loader: issue all cp.asyncs for tile t into stage st ----
    auto stage_tile = [&](int t, int st) {
        const int s0 = sbase + t * TILE_S;
        // inputs: 40 rows x 16 float4 (zero-fill out-of-range rows)
        #pragma unroll
        for (int idx = tid; idx < ROWS * 16; idx += NTHREADS) {
            const int r  = idx >> 4;
            const int cc = idx & 15;
            const int g  = s0 - (KS / 2) + r;
            const int ok = ((unsigned)g < (unsigned)S_LEN) ? 16 : 0;
            cp_async16z(&in_s[st][idx], &in_g[(size_t)g * ROW_F4 + cc], ok);
        }
        // filters: 32 rows x 3 aligned 16B chunks
        if (tid < TILE_S * 3) {
            const int r = tid / 3;
            const int q = tid - r * 3;
            cp_async16(&fraw[st][r * FP + q * 4],
                       f_g + (size_t)(s0 + r) * (H_NUM * KS) + q * 4);
        }
        asm volatile("cp.async.commit_group;\n" ::: "memory");
    };

    // ---- prologue: stage tile 0 ----
    stage_tile(0, 0);

    #pragma unroll
    for (int t = 0; t < NTILES; t++) {
        const int st = t & 1;
        const int s0 = sbase + t * TILE_S;

        // prefetch next tile into the other stage (overlaps this tile's use)
        if (t + 1 < NTILES) {
            stage_tile(t + 1, st ^ 1);
            asm volatile("cp.async.wait_group 1;\n" ::: "memory");
        } else {
            asm volatile("cp.async.wait_group 0;\n" ::: "memory");
        }
        __syncthreads();

        // softmax of this tile's taps (1 warp)
        if (tid < TILE_S) {
            float v[KS];
            float m = -1e30f;
            #pragma unroll
            for (int k = 0; k < KS; k++) {
                v[k] = fraw[st][tid * FP + shift + k];
                m = fmaxf(m, v[k]);
            }
            float sum = 0.f;
            #pragma unroll
            for (int k = 0; k < KS; k++) { v[k] = __expf(v[k] - m); sum += v[k]; }
            const float inv = 1.0f / sum;
            #pragma unroll
            for (int k = 0; k < KS; k++) w_s[tid * FP + k] = v[k] * inv;
        }
        __syncthreads();

        // conv: staged row sl0+j feeds output i at tap k = j - i
        float4 acc[SREG];
        #pragma unroll
        for (int i = 0; i < SREG; i++) acc[i] = make_float4(0.f, 0.f, 0.f, 0.f);

        #pragma unroll
        for (int j = 0; j < SREG + KS - 1; j++) {       // 12 rows
            const float4 r = in_s[st][(sl0 + j) * 16 + c];
            #pragma unroll
            for (int i = 0; i < SREG; i++) {
                const int k = j - i;
                if (k >= 0 && k < KS) {
                    const float w = w_s[(sl0 + i) * FP + k];
                    acc[i].x = fmaf(w, r.x, acc[i].x);
                    acc[i].y = fmaf(w, r.y, acc[i].y);
                    acc[i].z = fmaf(w, r.z, acc[i].z);
                    acc[i].w = fmaf(w, r.w, acc[i].w);
                }
            }
        }

        #pragma unroll
        for (int i = 0; i < SREG; i++)
            out_g[(size_t)(s0 + sl0 + i) * ROW_F4 + c] = acc[i];

        __syncthreads();   // protect w_s and the stage we'll overwrite next
    }
}

extern "C" void kernel_launch(void* const* d_in, const int* in_sizes, int n_in,
                              void* d_out, int out_size)
{
    const float* inputs  = (const float*)d_in[0];
    const float* filters = (const float*)d_in[1];
    if (n_in >= 2 && in_sizes[0] == 8 * 4096 * (H_NUM * KS)) {
        filters = (const float*)d_in[0];
        inputs  = (const float*)d_in[1];
    }
    float* out = (float*)d_out;

    dim3 grid(S_LEN / (TILE_S * NTILES), H_NUM, 8);   // 32 x 12 x 8 = 3072
    lightconv_kernel<<<grid, NTHREADS>>>(inputs, filters, out);
}

// round 10
// speedup vs baseline: 1.3250x; 1.3250x over previous
#include <cuda_runtime.h>

// ConvBertLightConv: dynamic depthwise conv, kernel=9, head=64.
// inputs:  [B=8, S=4096, D=768] fp32, filters: [B,S,108] fp32, out: [B,S,768].
//
// R9 (from R7 best): no cp.async at all, ONE barrier total.
//  - all threads front-batch their 12 input LDG.128s at kernel entry
//  - warp 0 concurrently LDGs the 9 raw taps per position, softmaxes in
//    registers, writes w_s; everyone else is already waiting at the barrier
//    with loads in flight -> softmax latency fully hidden
//  - streaming stores (st.global.cs) keep L2 for input-halo reuse

#define S_LEN   4096
#define D_DIM   768
#define H_NUM   12
#define HD      64
#define KS      9
#define TILE_S  32
#define SREG    4
#define NTHREADS 128                 // 8 position-groups x 16 f4-columns
#define NROWS   (SREG + KS - 1)      // 12
#define ROW_F4  (D_DIM / 4)          // 192
#define FP      12                   // padded filter row stride (floats)

__device__ __forceinline__ void stcs128(float4* p, float4 v) {
    asm volatile("st.global.cs.v4.f32 [%0], {%1,%2,%3,%4};\n"
                 :: "l"(p), "f"(v.x), "f"(v.y), "f"(v.z), "f"(v.w));
}

__global__ __launch_bounds__(NTHREADS, 6)
void lightconv_kernel(const float* __restrict__ inputs,
                      const float* __restrict__ filters,
                      float* __restrict__ out)
{
    __shared__ float w_s[TILE_S * FP];        // softmaxed taps, 1536 B

    const int tid = threadIdx.x;
    const int s0  = blockIdx.x * TILE_S;
    const int h   = blockIdx.y;
    const int b   = blockIdx.z;

    const int c   = tid & 15;                 // float4 column 0..15
    const int sl0 = (tid >> 4) * SREG;        // local base position

    // ---- front-batched input loads: 12 rows into registers ----
    const float4* in_g =
        (const float4*)(inputs + (size_t)b * S_LEN * D_DIM + h * HD);
    const int gbase = s0 + sl0 - (KS / 2);

    float4 rin[NROWS];
    if (s0 >= (KS / 2) && s0 + TILE_S + (KS / 2) <= S_LEN) {
        #pragma unroll
        for (int j = 0; j < NROWS; j++)
            rin[j] = __ldg(&in_g[(size_t)(gbase + j) * ROW_F4 + c]);
    } else {
        #pragma unroll
        for (int j = 0; j < NROWS; j++) {
            const int g = gbase + j;
            rin[j] = make_float4(0.f, 0.f, 0.f, 0.f);
            if (g >= 0 && g < S_LEN)
                rin[j] = __ldg(&in_g[(size_t)g * ROW_F4 + c]);
        }
    }

    // ---- warp 0: load taps, softmax, publish to w_s (overlaps rin LDGs) ----
    if (tid < TILE_S) {
        const float* f =
            filters + (size_t)(b * S_LEN + s0 + tid) * (H_NUM * KS) + h * KS;
        float v[KS];
        float m = -1e30f;
        #pragma unroll
        for (int k = 0; k < KS; k++) {
            v[k] = __ldg(f + k);
            m = fmaxf(m, v[k]);
        }
        float sum = 0.f;
        #pragma unroll
        for (int k = 0; k < KS; k++) { v[k] = __expf(v[k] - m); sum += v[k]; }
        const float inv = 1.0f / sum;
        #pragma unroll
        for (int k = 0; k < KS; k++) w_s[tid * FP + k] = v[k] * inv;
    }
    __syncthreads();                          // the ONLY barrier

    // ---- FMA: row j feeds output i at tap k = j - i ----
    float4 acc[SREG];
    #pragma unroll
    for (int i = 0; i < SREG; i++) acc[i] = make_float4(0.f, 0.f, 0.f, 0.f);

    #pragma unroll
    for (int j = 0; j < NROWS; j++) {
        const float4 r = rin[j];
        #pragma unroll
        for (int i = 0; i < SREG; i++) {
            const int k = j - i;
            if (k >= 0 && k < KS) {
                const float w = w_s[(sl0 + i) * FP + k];
                acc[i].x = fmaf(w, r.x, acc[i].x);
                acc[i].y = fmaf(w, r.y, acc[i].y);
                acc[i].z = fmaf(w, r.z, acc[i].z);
                acc[i].w = fmaf(w, r.w, acc[i].w);
            }
        }
    }

    // ---- streaming stores (256B-contiguous per position) ----
    float4* out_g = (float4*)(out + (size_t)b * S_LEN * D_DIM + h * HD);
    #pragma unroll
    for (int i = 0; i < SREG; i++)
        stcs128(&out_g[(size_t)(s0 + sl0 + i) * ROW_F4 + c], acc[i]);
}

extern "C" void kernel_launch(void* const* d_in, const int* in_sizes, int n_in,
                              void* d_out, int out_size)
{
    const float* inputs  = (const float*)d_in[0];
    const float* filters = (const float*)d_in[1];
    if (n_in >= 2 && in_sizes[0] == 8 * 4096 * (H_NUM * KS)) {
        filters = (const float*)d_in[0];
        inputs  = (const float*)d_in[1];
    }
    float* out = (float*)d_out;

    dim3 grid(S_LEN / TILE_S, H_NUM, 8);   // 128 x 12 x 8 = 12288 CTAs
    lightconv_kernel<<<grid, NTHREADS>>>(inputs, filters, out);
}